// round 2
// baseline (speedup 1.0000x reference)
#include <cuda_runtime.h>
#include <stdint.h>

#define NUM_TNETS 8388608
#define NUM_NODES 1048576

__global__ void zero_out_kernel(float4* __restrict__ out, int n4) {
    int i = blockIdx.x * blockDim.x + threadIdx.x;
    if (i < n4) out[i] = make_float4(0.f, 0.f, 0.f, 0.f);
}

__global__ void __launch_bounds__(256) scatter_add_kernel(
    const float* __restrict__ beta,          // [1]
    const float* __restrict__ tnet_weights,  // [NUM_TNETS]
    const int*   __restrict__ flat_tnet2pin, // [2*NUM_TNETS] int32
    const int*   __restrict__ pin2node,      // [NUM_PINS]    int32
    float* __restrict__ out)                 // [NUM_NODES]
{
    int t = blockIdx.x * blockDim.x + threadIdx.x;
    if (t >= NUM_TNETS) return;

    // coalesced 8B load: the (src, dst) pin pair of this timing arc
    int2 pins = __ldg(reinterpret_cast<const int2*>(flat_tnet2pin) + t);

    // weight scaled by beta (single scalar, L1/L2 hit)
    float w = __ldg(tnet_weights + t) * __ldg(beta);

    // two independent random gathers — 84MB table, mostly L2-resident
    int n0 = __ldg(pin2node + pins.x);
    int n1 = __ldg(pin2node + pins.y);

    atomicAdd(out + n0, w);
    atomicAdd(out + n1, w);
}

extern "C" void kernel_launch(void* const* d_in, const int* in_sizes, int n_in,
                              void* d_out, int out_size) {
    const float* beta         = (const float*)d_in[0];
    const float* tnet_weights = (const float*)d_in[1];
    const int*   flat_t2p     = (const int*)d_in[2];
    const int*   pin2node     = (const int*)d_in[3];
    float* out = (float*)d_out;

    // 1) zero the poisoned output (out_size = NUM_NODES, multiple of 4)
    {
        int n4 = out_size / 4;
        int threads = 256;
        int blocks = (n4 + threads - 1) / threads;
        zero_out_kernel<<<blocks, threads>>>((float4*)out, n4);
        // handle any non-multiple-of-4 tail (defensive; NUM_NODES % 4 == 0)
        if (out_size % 4) {
            cudaMemsetAsync(out + n4 * 4, 0, (out_size % 4) * sizeof(float));
        }
    }

    // 2) gather + atomic scatter-add, beta folded in
    {
        int threads = 256;
        int blocks = (NUM_TNETS + threads - 1) / threads;
        scatter_add_kernel<<<blocks, threads>>>(beta, tnet_weights, flat_t2p,
                                                pin2node, out);
    }
}

// round 3
// speedup vs baseline: 1.0742x; 1.0742x over previous
#include <cuda_runtime.h>
#include <stdint.h>

#define NUM_TNETS 8388608
#define NUM_NODES 1048576

// 2 tnets per thread: int4 = 4 pins, float2 = 2 weights.
// Streaming data uses evict-first (.cs) so the 84MB pin2node table keeps L2.
__global__ void __launch_bounds__(256) scatter_add_kernel(
    const float* __restrict__ beta,          // [1]
    const float* __restrict__ tnet_weights,  // [NUM_TNETS]
    const int*   __restrict__ flat_tnet2pin, // [2*NUM_TNETS] int32
    const int*   __restrict__ pin2node,      // [NUM_PINS]    int32
    float* __restrict__ out)                 // [NUM_NODES]
{
    int t = blockIdx.x * blockDim.x + threadIdx.x;  // pair index, 2 tnets each
    if (t >= NUM_TNETS / 2) return;

    // coalesced 16B streaming load: pins of two arcs [s0,d0,s1,d1]
    int4 pins = __ldcs(reinterpret_cast<const int4*>(flat_tnet2pin) + t);
    // coalesced 8B streaming load: the two arc weights
    float2 wv = __ldcs(reinterpret_cast<const float2*>(tnet_weights) + t);

    float b = __ldg(beta);
    float w0 = wv.x * b;
    float w1 = wv.y * b;

    // four independent random gathers (MLP=4) into the L2-resident table
    int n0 = __ldg(pin2node + pins.x);
    int n1 = __ldg(pin2node + pins.y);
    int n2 = __ldg(pin2node + pins.z);
    int n3 = __ldg(pin2node + pins.w);

    atomicAdd(out + n0, w0);
    atomicAdd(out + n1, w0);
    atomicAdd(out + n2, w1);
    atomicAdd(out + n3, w1);
}

extern "C" void kernel_launch(void* const* d_in, const int* in_sizes, int n_in,
                              void* d_out, int out_size) {
    const float* beta         = (const float*)d_in[0];
    const float* tnet_weights = (const float*)d_in[1];
    const int*   flat_t2p     = (const int*)d_in[2];
    const int*   pin2node     = (const int*)d_in[3];
    float* out = (float*)d_out;

    // 1) zero the poisoned output (async memset is graph-capturable)
    cudaMemsetAsync(out, 0, (size_t)out_size * sizeof(float));

    // 2) gather + atomic scatter-add, beta folded in
    {
        int threads = 256;
        int pairs = NUM_TNETS / 2;
        int blocks = (pairs + threads - 1) / threads;
        scatter_add_kernel<<<blocks, threads>>>(beta, tnet_weights, flat_t2p,
                                                pin2node, out);
    }
}